// round 1
// baseline (speedup 1.0000x reference)
#include <cuda_runtime.h>
#include <cstdint>

// Problem constants
#define BB 8
#define CC 96
#define HH 512
#define WW 96
#define HWX (HH*WW)     // 49152
#define OC  (3*CC)      // 288
#define SS  100         // smem row stride (floats), multiple of 4 for float4 stores

typedef unsigned long long u64;

__device__ __align__(16) float g_WT[CC*OC];   // W'^T: [c][o], BN folded in
__device__ float g_bias[OC];                  // effective bias

// ---------------- packed f32x2 helpers ----------------
__device__ __forceinline__ u64 ffma2(u64 a, u64 b, u64 c){
    u64 d; asm("fma.rn.f32x2 %0, %1, %2, %3;" : "=l"(d) : "l"(a), "l"(b), "l"(c)); return d;
}
__device__ __forceinline__ u64 pack2(float x){
    u64 d; asm("mov.b64 %0, {%1, %1};" : "=l"(d) : "f"(x)); return d;
}
__device__ __forceinline__ float2 unpack2(u64 a){
    float2 f; asm("mov.b64 {%0, %1}, %2;" : "=f"(f.x), "=f"(f.y) : "l"(a)); return f;
}

// ---------------- prep: fold BN into QKV weights ----------------
// grid = 288 blocks (one per output channel o), 96 threads (one per input channel c)
__global__ void prep_kernel(const float* __restrict__ qkv_w, const float* __restrict__ qkv_b,
                            const float* __restrict__ gam, const float* __restrict__ bet,
                            const float* __restrict__ mn,  const float* __restrict__ vr){
    int o = blockIdx.x;
    int c = threadIdx.x;
    __shared__ float red[CC];
    float inv   = gam[c] * rsqrtf(vr[c] + 1e-5f);
    float shift = bet[c] - mn[c]*inv;
    float wv = qkv_w[o*CC + c];
    g_WT[c*OC + o] = wv * inv;
    red[c] = wv * shift;
    __syncthreads();
    if (c < 32){
        float s = red[c] + red[c+32] + red[c+64];
        #pragma unroll
        for (int off = 16; off; off >>= 1) s += __shfl_down_sync(0xffffffffu, s, off);
        if (c == 0) g_bias[o] = s + qkv_b[o];
    }
}

// ---------------- fused attention kernel ----------------
// one CTA per (b,h). 256 threads: tx = t&15 (pair-cols), ty = t>>4 (rows)
__global__ __launch_bounds__(256) void attn_kernel(const float* __restrict__ x,
                                                   float* __restrict__ out){
    extern __shared__ float sm[];
    float* xs = sm;              // x tile            [c][w]  96 x SS
    float* ws = sm + 1*CC*SS;    // weights block, then score [q][k]
    float* qs = sm + 2*CC*SS;    // q [c][w]
    float* ks = sm + 3*CC*SS;    // k [c][w], later output buffer [c][w]
    float* vt = sm + 4*CC*SS;    // v transposed [w][c]

    const int t  = threadIdx.x;
    const int tx = t & 15;
    const int ty = t >> 4;
    const int bh = blockIdx.x;
    const int b  = bh >> 9;        // H = 512
    const int h  = bh & 511;
    const size_t base = (size_t)b*CC*HWX + (size_t)h*WW;

    // ---- load x tile (coalesced float4) ----
    for (int idx = t; idx < CC*24; idx += 256){
        int c = idx/24, j = idx%24;
        *(float4*)&xs[c*SS + 4*j] = *(const float4*)(x + base + (size_t)c*HWX + 4*j);
    }

    u64 acc[6][3];

    // ---- QKV GEMM: 3 passes (q, k, v) ----
    for (int p = 0; p < 3; ++p){
        __syncthreads();
        for (int idx = t; idx < CC*24; idx += 256){
            int c = idx/24, j = idx%24;
            *(float4*)&ws[c*SS + 4*j] = *(const float4*)&g_WT[c*OC + p*CC + 4*j];
        }
        __syncthreads();
        #pragma unroll
        for (int i = 0; i < 6; ++i){
            u64 b2 = pack2(g_bias[p*CC + ty + 16*i]);
            #pragma unroll
            for (int j = 0; j < 3; ++j) acc[i][j] = b2;
        }
        #pragma unroll 2
        for (int c = 0; c < CC; ++c){
            const float* xr = &xs[c*SS];
            const float* wr = &ws[c*SS];
            u64 bv[3];
            #pragma unroll
            for (int j = 0; j < 3; ++j) bv[j] = *(const u64*)&xr[2*tx + 32*j];
            #pragma unroll
            for (int i = 0; i < 6; ++i){
                u64 a2 = pack2(wr[ty + 16*i]);
                #pragma unroll
                for (int j = 0; j < 3; ++j) acc[i][j] = ffma2(a2, bv[j], acc[i][j]);
            }
        }
        if (p < 2){
            float* dst = (p == 0) ? qs : ks;
            #pragma unroll
            for (int i = 0; i < 6; ++i)
                #pragma unroll
                for (int j = 0; j < 3; ++j)
                    *(u64*)&dst[(ty + 16*i)*SS + 2*tx + 32*j] = acc[i][j];
        } else {
            // v: store transposed [w][o]
            #pragma unroll
            for (int i = 0; i < 6; ++i)
                #pragma unroll
                for (int j = 0; j < 3; ++j){
                    float2 f = unpack2(acc[i][j]);
                    int w0 = 2*tx + 32*j, o = ty + 16*i;
                    vt[(w0  )*SS + o] = f.x;
                    vt[(w0+1)*SS + o] = f.y;
                }
        }
    }

    // ---- score[q][k] = sum_c q[c][q] * k[c][k] ----
    __syncthreads();
    #pragma unroll
    for (int i = 0; i < 6; ++i)
        #pragma unroll
        for (int j = 0; j < 3; ++j) acc[i][j] = 0ull;
    #pragma unroll 2
    for (int c = 0; c < CC; ++c){
        const float* qr = &qs[c*SS];
        const float* kr = &ks[c*SS];
        u64 bv[3];
        #pragma unroll
        for (int j = 0; j < 3; ++j) bv[j] = *(const u64*)&kr[2*tx + 32*j];
        #pragma unroll
        for (int i = 0; i < 6; ++i){
            u64 a2 = pack2(qr[ty + 16*i]);
            #pragma unroll
            for (int j = 0; j < 3; ++j) acc[i][j] = ffma2(a2, bv[j], acc[i][j]);
        }
    }
    #pragma unroll
    for (int i = 0; i < 6; ++i)
        #pragma unroll
        for (int j = 0; j < 3; ++j)
            *(u64*)&ws[(ty + 16*i)*SS + 2*tx + 32*j] = acc[i][j];
    __syncthreads();

    // ---- softmax over k (rows of ws) ----
    {
        int warp = t >> 5, lane = t & 31;
        for (int r = warp*12; r < warp*12 + 12; ++r){
            float* row = &ws[r*SS];
            float v0 = row[lane], v1 = row[lane+32], v2 = row[lane+64];
            float m = fmaxf(v0, fmaxf(v1, v2));
            #pragma unroll
            for (int o2 = 16; o2; o2 >>= 1) m = fmaxf(m, __shfl_xor_sync(0xffffffffu, m, o2));
            float e0 = __expf(v0 - m), e1 = __expf(v1 - m), e2 = __expf(v2 - m);
            float s = e0 + e1 + e2;
            #pragma unroll
            for (int o2 = 16; o2; o2 >>= 1) s += __shfl_xor_sync(0xffffffffu, s, o2);
            float inv = 1.0f / s;
            row[lane] = e0*inv; row[lane+32] = e1*inv; row[lane+64] = e2*inv;
        }
    }
    __syncthreads();

    // ---- AV: out[c][q] = sum_k score[q][k] * vt[k][c] ----
    #pragma unroll
    for (int i = 0; i < 6; ++i)
        #pragma unroll
        for (int j = 0; j < 3; ++j) acc[i][j] = 0ull;
    #pragma unroll 2
    for (int k = 0; k < WW; ++k){
        const float* vr = &vt[k*SS];
        u64 bv[3];
        #pragma unroll
        for (int j = 0; j < 3; ++j) bv[j] = *(const u64*)&vr[2*tx + 32*j];
        #pragma unroll
        for (int i = 0; i < 6; ++i){
            u64 a2 = pack2(ws[(ty + 16*i)*SS + k]);
            #pragma unroll
            for (int j = 0; j < 3; ++j) acc[i][j] = ffma2(a2, bv[j], acc[i][j]);
        }
    }
    // epilogue: residual add, write [c][q] into ks (free buffer)
    #pragma unroll
    for (int i = 0; i < 6; ++i)
        #pragma unroll
        for (int j = 0; j < 3; ++j){
            float2 f = unpack2(acc[i][j]);
            int c0 = 2*tx + 32*j, q = ty + 16*i;
            ks[(c0  )*SS + q] = f.x + xs[(c0  )*SS + q];
            ks[(c0+1)*SS + q] = f.y + xs[(c0+1)*SS + q];
        }
    __syncthreads();

    // ---- coalesced writeout ----
    for (int idx = t; idx < CC*24; idx += 256){
        int c = idx/24, j = idx%24;
        *(float4*)(out + base + (size_t)c*HWX + 4*j) = *(const float4*)&ks[c*SS + 4*j];
    }
}

extern "C" void kernel_launch(void* const* d_in, const int* in_sizes, int n_in,
                              void* d_out, int out_size){
    const float* x     = (const float*)d_in[0];
    const float* gam   = (const float*)d_in[1];
    const float* bet   = (const float*)d_in[2];
    const float* mn    = (const float*)d_in[3];
    const float* vr    = (const float*)d_in[4];
    const float* qkv_w = (const float*)d_in[5];
    const float* qkv_b = (const float*)d_in[6];
    float* out = (float*)d_out;

    cudaFuncSetAttribute(attn_kernel, cudaFuncAttributeMaxDynamicSharedMemorySize, CC*SS*5*sizeof(float));

    prep_kernel<<<OC, CC>>>(qkv_w, qkv_b, gam, bet, mn, vr);
    attn_kernel<<<BB*HH, 256, CC*SS*5*sizeof(float)>>>(x, out);
}

// round 2
// speedup vs baseline: 1.0112x; 1.0112x over previous
#include <cuda_runtime.h>
#include <cstdint>

// Problem constants
#define BB 8
#define CC 96
#define HH 512
#define WW 96
#define HWX (HH*WW)     // 49152
#define OC  (3*CC)      // 288
#define SS  100         // smem row stride (floats)

typedef unsigned long long u64;

__device__ __align__(16) float g_WT[CC*OC];   // W'^T: [c][o], BN folded in
__device__ float g_bias[OC];                  // effective bias

// ---------------- packed f32x2 helpers ----------------
__device__ __forceinline__ u64 ffma2(u64 a, u64 b, u64 c){
    u64 d; asm("fma.rn.f32x2 %0, %1, %2, %3;" : "=l"(d) : "l"(a), "l"(b), "l"(c)); return d;
}
__device__ __forceinline__ u64 pack2(float x){
    u64 d; asm("mov.b64 %0, {%1, %1};" : "=l"(d) : "f"(x)); return d;
}
__device__ __forceinline__ float2 unpack2(u64 a){
    float2 f; asm("mov.b64 {%0, %1}, %2;" : "=f"(f.x), "=f"(f.y) : "l"(a)); return f;
}

// ---------------- prep: fold BN into QKV weights ----------------
__global__ void prep_kernel(const float* __restrict__ qkv_w, const float* __restrict__ qkv_b,
                            const float* __restrict__ gam, const float* __restrict__ bet,
                            const float* __restrict__ mn,  const float* __restrict__ vr){
    int o = blockIdx.x;
    int c = threadIdx.x;
    __shared__ float red[CC];
    float inv   = gam[c] * rsqrtf(vr[c] + 1e-5f);
    float shift = bet[c] - mn[c]*inv;
    float wv = qkv_w[o*CC + c];
    g_WT[c*OC + o] = wv * inv;
    red[c] = wv * shift;
    __syncthreads();
    if (c < 32){
        float s = red[c] + red[c+32] + red[c+64];
        #pragma unroll
        for (int off = 16; off; off >>= 1) s += __shfl_down_sync(0xffffffffu, s, off);
        if (c == 0) g_bias[o] = s + qkv_b[o];
    }
}

// ---------------- fused attention kernel ----------------
// one CTA per (b,h). 512 threads: tx = t&15 (pair-cols), ty = t>>4 in [0,32)
// thread tile: rows ty+32*i (i<3), col pairs 2*tx+32*j (j<3)
__global__ __launch_bounds__(512) void attn_kernel(const float* __restrict__ x,
                                                   float* __restrict__ out){
    extern __shared__ float sm[];
    float* xs = sm;              // x tile [c][w]
    float* ws = sm + 1*CC*SS;    // weights block, then score [q][k]
    float* qs = sm + 2*CC*SS;    // q [c][w]
    float* ks = sm + 3*CC*SS;    // k [c][w], later output buffer [c][w]
    float* vt = sm + 4*CC*SS;    // v transposed [w][c]

    const int t  = threadIdx.x;
    const int tx = t & 15;
    const int ty = t >> 4;       // 0..31
    const int bh = blockIdx.x;
    const int b  = bh >> 9;      // H = 512
    const int h  = bh & 511;
    const size_t base = (size_t)b*CC*HWX + (size_t)h*WW;

    // ---- load x tile (coalesced float4) ----
    for (int idx = t; idx < CC*24; idx += 512){
        int c = idx/24, j = idx%24;
        *(float4*)&xs[c*SS + 4*j] = *(const float4*)(x + base + (size_t)c*HWX + 4*j);
    }

    u64 acc[3][3];

    // ---- QKV GEMM: 3 passes (q, k, v) ----
    for (int p = 0; p < 3; ++p){
        __syncthreads();
        for (int idx = t; idx < CC*24; idx += 512){
            int c = idx/24, j = idx%24;
            *(float4*)&ws[c*SS + 4*j] = *(const float4*)&g_WT[c*OC + p*CC + 4*j];
        }
        __syncthreads();
        #pragma unroll
        for (int i = 0; i < 3; ++i){
            u64 b2 = pack2(g_bias[p*CC + ty + 32*i]);
            #pragma unroll
            for (int j = 0; j < 3; ++j) acc[i][j] = b2;
        }
        #pragma unroll 4
        for (int c = 0; c < CC; ++c){
            const float* xr = &xs[c*SS];
            const float* wr = &ws[c*SS];
            u64 bv[3];
            #pragma unroll
            for (int j = 0; j < 3; ++j) bv[j] = *(const u64*)&xr[2*tx + 32*j];
            #pragma unroll
            for (int i = 0; i < 3; ++i){
                u64 a2 = pack2(wr[ty + 32*i]);
                #pragma unroll
                for (int j = 0; j < 3; ++j) acc[i][j] = ffma2(a2, bv[j], acc[i][j]);
            }
        }
        if (p < 2){
            float* dst = (p == 0) ? qs : ks;
            #pragma unroll
            for (int i = 0; i < 3; ++i)
                #pragma unroll
                for (int j = 0; j < 3; ++j)
                    *(u64*)&dst[(ty + 32*i)*SS + 2*tx + 32*j] = acc[i][j];
        } else {
            // v: store transposed [w][o]
            #pragma unroll
            for (int i = 0; i < 3; ++i)
                #pragma unroll
                for (int j = 0; j < 3; ++j){
                    float2 f = unpack2(acc[i][j]);
                    int w0 = 2*tx + 32*j, o = ty + 32*i;
                    vt[(w0  )*SS + o] = f.x;
                    vt[(w0+1)*SS + o] = f.y;
                }
        }
    }

    // ---- score[q][k] = sum_c q[c][q] * k[c][k] ----
    __syncthreads();
    #pragma unroll
    for (int i = 0; i < 3; ++i)
        #pragma unroll
        for (int j = 0; j < 3; ++j) acc[i][j] = 0ull;
    #pragma unroll 4
    for (int c = 0; c < CC; ++c){
        const float* qr = &qs[c*SS];
        const float* kr = &ks[c*SS];
        u64 bv[3];
        #pragma unroll
        for (int j = 0; j < 3; ++j) bv[j] = *(const u64*)&kr[2*tx + 32*j];
        #pragma unroll
        for (int i = 0; i < 3; ++i){
            u64 a2 = pack2(qr[ty + 32*i]);
            #pragma unroll
            for (int j = 0; j < 3; ++j) acc[i][j] = ffma2(a2, bv[j], acc[i][j]);
        }
    }
    #pragma unroll
    for (int i = 0; i < 3; ++i)
        #pragma unroll
        for (int j = 0; j < 3; ++j)
            *(u64*)&ws[(ty + 32*i)*SS + 2*tx + 32*j] = acc[i][j];
    __syncthreads();

    // ---- softmax over k (rows of ws): 16 warps x 6 rows ----
    {
        int warp = t >> 5, lane = t & 31;
        for (int r = warp*6; r < warp*6 + 6; ++r){
            float* row = &ws[r*SS];
            float v0 = row[lane], v1 = row[lane+32], v2 = row[lane+64];
            float m = fmaxf(v0, fmaxf(v1, v2));
            #pragma unroll
            for (int o2 = 16; o2; o2 >>= 1) m = fmaxf(m, __shfl_xor_sync(0xffffffffu, m, o2));
            float e0 = __expf(v0 - m), e1 = __expf(v1 - m), e2 = __expf(v2 - m);
            float s = e0 + e1 + e2;
            #pragma unroll
            for (int o2 = 16; o2; o2 >>= 1) s += __shfl_xor_sync(0xffffffffu, s, o2);
            float inv = 1.0f / s;
            row[lane] = e0*inv; row[lane+32] = e1*inv; row[lane+64] = e2*inv;
        }
    }
    __syncthreads();

    // ---- AV: out[c][q] = sum_k score[q][k] * vt[k][c] ----
    #pragma unroll
    for (int i = 0; i < 3; ++i)
        #pragma unroll
        for (int j = 0; j < 3; ++j) acc[i][j] = 0ull;
    #pragma unroll 4
    for (int k = 0; k < WW; ++k){
        const float* vr = &vt[k*SS];
        u64 bv[3];
        #pragma unroll
        for (int j = 0; j < 3; ++j) bv[j] = *(const u64*)&vr[2*tx + 32*j];
        #pragma unroll
        for (int i = 0; i < 3; ++i){
            u64 a2 = pack2(ws[(ty + 32*i)*SS + k]);
            #pragma unroll
            for (int j = 0; j < 3; ++j) acc[i][j] = ffma2(a2, bv[j], acc[i][j]);
        }
    }
    // epilogue: residual add, write [c][q] into ks (free buffer)
    #pragma unroll
    for (int i = 0; i < 3; ++i)
        #pragma unroll
        for (int j = 0; j < 3; ++j){
            float2 f = unpack2(acc[i][j]);
            int c0 = 2*tx + 32*j, q = ty + 32*i;
            ks[(c0  )*SS + q] = f.x + xs[(c0  )*SS + q];
            ks[(c0+1)*SS + q] = f.y + xs[(c0+1)*SS + q];
        }
    __syncthreads();

    // ---- coalesced writeout ----
    for (int idx = t; idx < CC*24; idx += 512){
        int c = idx/24, j = idx%24;
        *(float4*)(out + base + (size_t)c*HWX + 4*j) = *(const float4*)&ks[c*SS + 4*j];
    }
}

extern "C" void kernel_launch(void* const* d_in, const int* in_sizes, int n_in,
                              void* d_out, int out_size){
    const float* x     = (const float*)d_in[0];
    const float* gam   = (const float*)d_in[1];
    const float* bet   = (const float*)d_in[2];
    const float* mn    = (const float*)d_in[3];
    const float* vr    = (const float*)d_in[4];
    const float* qkv_w = (const float*)d_in[5];
    const float* qkv_b = (const float*)d_in[6];
    float* out = (float*)d_out;

    cudaFuncSetAttribute(attn_kernel, cudaFuncAttributeMaxDynamicSharedMemorySize, CC*SS*5*sizeof(float));

    prep_kernel<<<OC, CC>>>(qkv_w, qkv_b, gam, bet, mn, vr);
    attn_kernel<<<BB*HH, 512, CC*SS*5*sizeof(float)>>>(x, out);
}